// round 1
// baseline (speedup 1.0000x reference)
#include <cuda_runtime.h>

#define CENTER_X 0.5f
#define B 256
#define N 512

// Per-batch partial results: .x = total loss, .y = pair count.
// Fully overwritten by pass1 on every launch -> deterministic, no init needed.
__device__ double2 g_partials[B];

__global__ __launch_bounds__(N) void sym_pass1(const float2* __restrict__ kp,
                                               const int* __restrict__ cls) {
    const int b = blockIdx.x;
    const int i = threadIdx.x;

    const float2 p = kp[b * N + i];
    const int    c = cls[b * N + i];
    const float  u = p.x - CENTER_X;
    const float  y = p.y;

    // 3 symmetric classes x {m, su, su2, sy, sy2}
    float acc[15];
#pragma unroll
    for (int k = 0; k < 3; k++) {
        const float v = (c == k) ? 1.0f : 0.0f;
        acc[k * 5 + 0] = v;
        acc[k * 5 + 1] = v * u;
        acc[k * 5 + 2] = v * u * u;
        acc[k * 5 + 3] = v * y;
        acc[k * 5 + 4] = v * y * y;
    }

    // warp reduction of all 15 quantities
#pragma unroll
    for (int j = 0; j < 15; j++) {
#pragma unroll
        for (int off = 16; off > 0; off >>= 1)
            acc[j] += __shfl_xor_sync(0xffffffffu, acc[j], off);
    }

    __shared__ float s[16][15];
    const int warp = i >> 5;
    const int lane = i & 31;
    if (lane == 0) {
#pragma unroll
        for (int j = 0; j < 15; j++) s[warp][j] = acc[j];
    }
    __syncthreads();

    if (i == 0) {
        double tot = 0.0, cnt = 0.0;
#pragma unroll
        for (int k = 0; k < 3; k++) {
            double m = 0.0, su = 0.0, su2 = 0.0, sy = 0.0, sy2 = 0.0;
            for (int w = 0; w < 16; w++) {
                m   += (double)s[w][k * 5 + 0];
                su  += (double)s[w][k * 5 + 1];
                su2 += (double)s[w][k * 5 + 2];
                sy  += (double)s[w][k * 5 + 3];
                sy2 += (double)s[w][k * 5 + 4];
            }
            // sum_{i<j} (u_i+u_j)^2 = (m-2)*su2 + su^2
            // sum_{i<j} (y_i-y_j)^2 = m*sy2 - sy^2
            tot += (m - 2.0) * su2 + su * su + m * sy2 - sy * sy;
            cnt += m * (m - 1.0) * 0.5;
        }
        g_partials[b] = make_double2(tot, cnt);
    }
}

__global__ __launch_bounds__(B) void sym_pass2(float* __restrict__ out) {
    const int i = threadIdx.x;
    double2 p = g_partials[i];

#pragma unroll
    for (int off = 16; off > 0; off >>= 1) {
        p.x += __shfl_xor_sync(0xffffffffu, p.x, off);
        p.y += __shfl_xor_sync(0xffffffffu, p.y, off);
    }

    __shared__ double2 s[8];
    const int warp = i >> 5;
    const int lane = i & 31;
    if (lane == 0) s[warp] = p;
    __syncthreads();

    if (i == 0) {
        double tot = 0.0, cnt = 0.0;
#pragma unroll
        for (int w = 0; w < 8; w++) {
            tot += s[w].x;
            cnt += s[w].y;
        }
        out[0] = (float)(tot / fmax(cnt, 1.0));
    }
}

extern "C" void kernel_launch(void* const* d_in, const int* in_sizes, int n_in,
                              void* d_out, int out_size) {
    const float2* kp  = (const float2*)d_in[0];   // [B, N, 2] f32 -> float2
    const int*    cls = (const int*)d_in[1];      // [B, N] i32
    float*        out = (float*)d_out;            // scalar

    sym_pass1<<<B, N>>>(kp, cls);
    sym_pass2<<<1, B>>>(out);
}

// round 3
// speedup vs baseline: 2.4328x; 2.4328x over previous
#include <cuda_runtime.h>

#define CENTER_X 0.5f
#define B 256
#define N 512

// Per-batch partials (.x = loss sum, .y = pair count) + arrival ticket.
// g_part fully overwritten each launch; g_ticket reset to 0 by the last
// block each launch -> deterministic across graph replays.
__device__ double2  g_part[B];
__device__ unsigned g_ticket = 0;

__global__ __launch_bounds__(N) void sym_fused(const float2* __restrict__ kp,
                                               const int* __restrict__ cls,
                                               float* __restrict__ out) {
    const int b    = blockIdx.x;
    const int i    = threadIdx.x;
    const int warp = i >> 5;
    const int lane = i & 31;

    const float2 p = kp[b * N + i];
    const int    c = cls[b * N + i];
    const float  u = p.x - CENTER_X;
    const float  y = p.y;

    // Per symmetric class k in {0,1,2}: {su, su2, sy, sy2}; count via ballot.
    float acc[12];
    float mcnt[3];
#pragma unroll
    for (int k = 0; k < 3; k++) {
        const bool     in  = (c == k);
        const unsigned bal = __ballot_sync(0xffffffffu, in);
        mcnt[k] = (float)__popc(bal);
        const float v = in ? 1.0f : 0.0f;
        acc[k * 4 + 0] = v * u;
        acc[k * 4 + 1] = v * u * u;
        acc[k * 4 + 2] = v * y;
        acc[k * 4 + 3] = v * y * y;
    }

    // Intra-warp reduction of the 12 float sums.
#pragma unroll
    for (int j = 0; j < 12; j++) {
#pragma unroll
        for (int off = 16; off > 0; off >>= 1)
            acc[j] += __shfl_xor_sync(0xffffffffu, acc[j], off);
    }

    __shared__ float s[16][16];  // 16 warps x 15 stats (padded to 16)
    if (lane == 0) {
#pragma unroll
        for (int j = 0; j < 12; j++) s[warp][j] = acc[j];
        s[warp][12] = mcnt[0];
        s[warp][13] = mcnt[1];
        s[warp][14] = mcnt[2];
    }
    __syncthreads();

    // Warp 0 combines the 16 warp partials with a shuffle tree (no serial tail).
    if (warp == 0) {
        float v[15];
#pragma unroll
        for (int j = 0; j < 15; j++) v[j] = (lane < 16) ? s[lane][j] : 0.0f;
#pragma unroll
        for (int j = 0; j < 15; j++) {
#pragma unroll
            for (int off = 8; off > 0; off >>= 1)
                v[j] += __shfl_xor_sync(0x0000ffffu, v[j], off);
        }
        if (lane == 0) {
            double tot = 0.0, cnt = 0.0;
#pragma unroll
            for (int k = 0; k < 3; k++) {
                const double su  = v[k * 4 + 0];
                const double su2 = v[k * 4 + 1];
                const double sy  = v[k * 4 + 2];
                const double sy2 = v[k * 4 + 3];
                const double m   = v[12 + k];
                // sum_{i<j}(u_i+u_j)^2 = (m-2)*su2 + su^2
                // sum_{i<j}(y_i-y_j)^2 = m*sy2 - sy^2
                tot += (m - 2.0) * su2 + su * su + m * sy2 - sy * sy;
                cnt += m * (m - 1.0) * 0.5;
            }
            g_part[b] = make_double2(tot, cnt);
        }
    }

    // Last arriving block performs the final 256-way reduction.
    __shared__ bool isLast;
    if (i == 0) {
        __threadfence();  // make g_part[b] visible before the ticket
        const unsigned t = atomicAdd(&g_ticket, 1u);
        isLast = (t == (unsigned)(gridDim.x - 1));
    }
    __syncthreads();

    if (isLast) {
        if (i == 0) g_ticket = 0;  // reset for next graph replay

        double tx = 0.0, ty = 0.0;
        if (i < B) {
            const double2 q = g_part[i];
            tx = q.x;
            ty = q.y;
        }
#pragma unroll
        for (int off = 16; off > 0; off >>= 1) {
            tx += __shfl_xor_sync(0xffffffffu, tx, off);
            ty += __shfl_xor_sync(0xffffffffu, ty, off);
        }
        __shared__ double2 sd[16];
        if (lane == 0) sd[warp] = make_double2(tx, ty);
        __syncthreads();
        if (warp == 0) {
            double a  = (lane < 16) ? sd[lane].x : 0.0;
            double bb = (lane < 16) ? sd[lane].y : 0.0;
#pragma unroll
            for (int off = 8; off > 0; off >>= 1) {
                a  += __shfl_xor_sync(0x0000ffffu, a, off);
                bb += __shfl_xor_sync(0x0000ffffu, bb, off);
            }
            if (lane == 0) out[0] = (float)(a / fmax(bb, 1.0));
        }
    }
}

extern "C" void kernel_launch(void* const* d_in, const int* in_sizes, int n_in,
                              void* d_out, int out_size) {
    const float2* kp  = (const float2*)d_in[0];  // [B, N, 2] f32
    const int*    cls = (const int*)d_in[1];     // [B, N] i32
    float*        out = (float*)d_out;           // scalar f32

    sym_fused<<<B, N>>>(kp, cls, out);
}

// round 4
// speedup vs baseline: 3.8925x; 1.6000x over previous
#include <cuda_runtime.h>

#define CENTER_X 0.5f
#define BATCHES  256
#define NPTS     512
#define BLOCKS   64
#define TPB      128   // 4 warps -> 4 batches per block

// Per-block partials (.x = loss sum, .y = pair count) + arrival ticket.
// Fully overwritten each launch; ticket reset by last block -> deterministic.
__device__ double2  g_part[BLOCKS];
__device__ unsigned g_ticket = 0;

__global__ __launch_bounds__(TPB) void sym_fused(const float4* __restrict__ kp4,
                                                 const int2*   __restrict__ cls2,
                                                 float*        __restrict__ out) {
    const int lane  = threadIdx.x & 31;
    const int warp  = threadIdx.x >> 5;
    const int batch = blockIdx.x * 4 + warp;   // one warp owns one batch

    const float4* kp = kp4  + batch * (NPTS / 2);
    const int2*   cl = cls2 + batch * (NPTS / 2);

    // Per symmetric class k in {0,1,2}: {m, su, su2, sy, sy2}
    float m[3]  = {0.f, 0.f, 0.f};
    float su[3] = {0.f, 0.f, 0.f};
    float s2[3] = {0.f, 0.f, 0.f};
    float sy[3] = {0.f, 0.f, 0.f};
    float q2[3] = {0.f, 0.f, 0.f};

#pragma unroll
    for (int j = 0; j < 8; j++) {
        const int    idx = j * 32 + lane;      // pair index m -> points 2m, 2m+1
        const float4 p   = kp[idx];
        const int2   c   = cl[idx];

        const float ua = p.x - CENTER_X, ya = p.y;
        const float ub = p.z - CENTER_X, yb = p.w;
        const float ua2 = ua * ua, ya2 = ya * ya;
        const float ub2 = ub * ub, yb2 = yb * yb;

#pragma unroll
        for (int k = 0; k < 3; k++) {
            const float fa = (c.x == k) ? 1.f : 0.f;
            const float fb = (c.y == k) ? 1.f : 0.f;
            m[k]  += fa + fb;
            su[k]  = fmaf(fa, ua,  fmaf(fb, ub,  su[k]));
            s2[k]  = fmaf(fa, ua2, fmaf(fb, ub2, s2[k]));
            sy[k]  = fmaf(fa, ya,  fmaf(fb, yb,  sy[k]));
            q2[k]  = fmaf(fa, ya2, fmaf(fb, yb2, q2[k]));
        }
    }

    // Warp-local butterfly over the 15 sums (whole batch lives in this warp).
#pragma unroll
    for (int off = 16; off > 0; off >>= 1) {
#pragma unroll
        for (int k = 0; k < 3; k++) {
            m[k]  += __shfl_xor_sync(0xffffffffu, m[k],  off);
            su[k] += __shfl_xor_sync(0xffffffffu, su[k], off);
            s2[k] += __shfl_xor_sync(0xffffffffu, s2[k], off);
            sy[k] += __shfl_xor_sync(0xffffffffu, sy[k], off);
            q2[k] += __shfl_xor_sync(0xffffffffu, q2[k], off);
        }
    }

    // Lane 0: closed-form pair sums for this batch, in double.
    __shared__ double2 s_part[4];
    if (lane == 0) {
        double tot = 0.0, cnt = 0.0;
#pragma unroll
        for (int k = 0; k < 3; k++) {
            const double dm  = m[k],  dsu = su[k], ds2 = s2[k];
            const double dsy = sy[k], dq2 = q2[k];
            // sum_{i<j}(u_i+u_j)^2 = (m-2)*su2 + su^2
            // sum_{i<j}(y_i-y_j)^2 = m*sy2 - sy^2
            tot += (dm - 2.0) * ds2 + dsu * dsu + dm * dq2 - dsy * dsy;
            cnt += dm * (dm - 1.0) * 0.5;
        }
        s_part[warp] = make_double2(tot, cnt);
    }
    __syncthreads();

    __shared__ bool isLast;
    if (threadIdx.x == 0) {
        double tot = 0.0, cnt = 0.0;
#pragma unroll
        for (int w = 0; w < 4; w++) { tot += s_part[w].x; cnt += s_part[w].y; }
        g_part[blockIdx.x] = make_double2(tot, cnt);
        __threadfence();
        isLast = (atomicAdd(&g_ticket, 1u) == (unsigned)(BLOCKS - 1));
    }
    __syncthreads();

    // Last block: reduce the 64 block partials with one warp.
    if (isLast && warp == 0) {
        if (lane == 0) g_ticket = 0;           // reset for next replay
        __threadfence();                        // acquire side

        const double2 a = g_part[lane];
        const double2 b = g_part[lane + 32];
        double tx = a.x + b.x;
        double ty = a.y + b.y;
#pragma unroll
        for (int off = 16; off > 0; off >>= 1) {
            tx += __shfl_xor_sync(0xffffffffu, tx, off);
            ty += __shfl_xor_sync(0xffffffffu, ty, off);
        }
        if (lane == 0) out[0] = (float)(tx / fmax(ty, 1.0));
    }
}

extern "C" void kernel_launch(void* const* d_in, const int* in_sizes, int n_in,
                              void* d_out, int out_size) {
    const float4* kp  = (const float4*)d_in[0];  // [256, 512, 2] f32 -> float4 pairs
    const int2*   cls = (const int2*)d_in[1];    // [256, 512] i32 -> int2 pairs
    float*        out = (float*)d_out;           // scalar f32

    sym_fused<<<BLOCKS, TPB>>>(kp, cls, out);
}

// round 5
// speedup vs baseline: 5.0347x; 1.2934x over previous
#include <cuda_runtime.h>

#define CENTER_X 0.5f
#define NPTS    512
#define NWARPS  256   // one warp per batch
#define BLOCKS  64
#define TPB     128

// Cross-launch accumulators. Winner warp resets both each launch, so state is
// identical at the start of every graph replay. No allocation, no init kernel.
__device__ float              g_tot    = 0.0f;
__device__ unsigned long long g_ticket = 0ull;  // bits[0:9)=arrivals, bits[9:64)=pair count

__global__ __launch_bounds__(TPB) void sym_fused(const float4* __restrict__ kp4,
                                                 const int2*   __restrict__ cls2,
                                                 float*        __restrict__ out) {
    const int lane  = threadIdx.x & 31;
    const int batch = (blockIdx.x * TPB + threadIdx.x) >> 5;  // global warp id

    const float4* kp = kp4  + batch * (NPTS / 2);
    const int2*   cl = cls2 + batch * (NPTS / 2);

    // Per symmetric class k in {0,1,2}: {m, su, su2, sy, sy2}
    float m[3]  = {0.f, 0.f, 0.f};
    float su[3] = {0.f, 0.f, 0.f};
    float s2[3] = {0.f, 0.f, 0.f};
    float sy[3] = {0.f, 0.f, 0.f};
    float q2[3] = {0.f, 0.f, 0.f};

#pragma unroll
    for (int j = 0; j < 8; j++) {
        const int    idx = j * 32 + lane;
        const float4 p   = kp[idx];
        const int2   c   = cl[idx];

        const float ua = p.x - CENTER_X, ya = p.y;
        const float ub = p.z - CENTER_X, yb = p.w;
        const float ua2 = ua * ua, ya2 = ya * ya;
        const float ub2 = ub * ub, yb2 = yb * yb;

#pragma unroll
        for (int k = 0; k < 3; k++) {
            const float fa = (c.x == k) ? 1.f : 0.f;
            const float fb = (c.y == k) ? 1.f : 0.f;
            m[k]  += fa + fb;
            su[k]  = fmaf(fa, ua,  fmaf(fb, ub,  su[k]));
            s2[k]  = fmaf(fa, ua2, fmaf(fb, ub2, s2[k]));
            sy[k]  = fmaf(fa, ya,  fmaf(fb, yb,  sy[k]));
            q2[k]  = fmaf(fa, ya2, fmaf(fb, yb2, q2[k]));
        }
    }

    // Warp-local butterfly (whole batch lives in this warp).
#pragma unroll
    for (int off = 16; off > 0; off >>= 1) {
#pragma unroll
        for (int k = 0; k < 3; k++) {
            m[k]  += __shfl_xor_sync(0xffffffffu, m[k],  off);
            su[k] += __shfl_xor_sync(0xffffffffu, su[k], off);
            s2[k] += __shfl_xor_sync(0xffffffffu, s2[k], off);
            sy[k] += __shfl_xor_sync(0xffffffffu, sy[k], off);
            q2[k] += __shfl_xor_sync(0xffffffffu, q2[k], off);
        }
    }

    if (lane == 0) {
        float    tot = 0.f;
        unsigned cnt = 0u;
#pragma unroll
        for (int k = 0; k < 3; k++) {
            // sum_{i<j}(u_i+u_j)^2 = (m-2)*su2 + su^2
            // sum_{i<j}(y_i-y_j)^2 = m*sy2 - sy^2
            tot += (m[k] - 2.f) * s2[k] + su[k] * su[k] + m[k] * q2[k] - sy[k] * sy[k];
            cnt += (unsigned)(m[k] * (m[k] - 1.f) * 0.5f);  // exact: m<=512 integer-valued
        }

        atomicAdd(&g_tot, tot);          // fire-and-forget (REDG-like)
        __threadfence();                 // release: g_tot add visible before ticket

        const unsigned long long pkt = ((unsigned long long)cnt << 9) | 1ull;
        const unsigned long long old = atomicAdd(&g_ticket, pkt);

        if ((old & 0x1FFull) == (unsigned long long)(NWARPS - 1)) {
            // This warp is the last arriver: all 255 other g_tot adds are
            // fenced-before their ticket adds, which we have observed.
            __threadfence();  // acquire
            const unsigned long long fin = old + pkt;
            const float fcnt = (float)(unsigned)(fin >> 9);  // exact global pair count
            const float ftot = *(volatile float*)&g_tot;     // strong load, bypasses L1
            out[0] = ftot / fmaxf(fcnt, 1.0f);
            // Reset for the next graph replay (kernel boundary publishes these).
            g_tot    = 0.0f;
            g_ticket = 0ull;
        }
    }
}

extern "C" void kernel_launch(void* const* d_in, const int* in_sizes, int n_in,
                              void* d_out, int out_size) {
    const float4* kp  = (const float4*)d_in[0];  // [256, 512, 2] f32 -> float4 = 2 points
    const int2*   cls = (const int2*)d_in[1];    // [256, 512] i32 -> int2 = 2 classes
    float*        out = (float*)d_out;           // scalar f32

    sym_fused<<<BLOCKS, TPB>>>(kp, cls, out);
}

// round 8
// speedup vs baseline: 6.0935x; 1.2103x over previous
#include <cuda_runtime.h>

#define CENTER_X 0.5f
#define NPTS    512
#define NWARPS  256   // one warp per batch
#define BLOCKS  64
#define TPB     128
#define FPSCALE 1048576.0f       // 2^20 lane-partial fixed-point scale
#define FPINV   (1.0f / 1048576.0f)

// Single packed accumulator:
//   bits [0:9)   arrival count (256 warps)
//   bits [9:32)  exact integer pair count (sum over batches)
//   bits [32:64) fixed-point loss sum, scale 2^11
// Winner decodes the final value straight from its atomicAdd return -> no
// fences, no second accumulator, order-independent (bitwise deterministic).
// Reset to 0 by the winner each launch -> identical state every graph replay.
__device__ unsigned long long g_acc = 0ull;

__global__ __launch_bounds__(TPB) void sym_fused(const float4* __restrict__ kp4,
                                                 const int2*   __restrict__ cls2,
                                                 float*        __restrict__ out) {
    const int lane  = threadIdx.x & 31;
    const int batch = (blockIdx.x * TPB + threadIdx.x) >> 5;  // global warp id

    const float4* kp = kp4  + batch * (NPTS / 2);
    const int2*   cl = cls2 + batch * (NPTS / 2);

    // Per symmetric class k in {0,1,2}: {m(int), su, su2, sy, sy2}
    float su[3] = {0.f, 0.f, 0.f};
    float s2[3] = {0.f, 0.f, 0.f};
    float sy[3] = {0.f, 0.f, 0.f};
    float q2[3] = {0.f, 0.f, 0.f};
    int   mi[3] = {0, 0, 0};

#pragma unroll
    for (int j = 0; j < 8; j++) {
        const int    idx = j * 32 + lane;
        const float4 p   = kp[idx];
        const int2   c   = cl[idx];

        const float ua = p.x - CENTER_X, ya = p.y;
        const float ub = p.z - CENTER_X, yb = p.w;
        const float ua2 = ua * ua, ya2 = ya * ya;
        const float ub2 = ub * ub, yb2 = yb * yb;

#pragma unroll
        for (int k = 0; k < 3; k++) {
            const bool  ia = (c.x == k), ib = (c.y == k);
            const float fa = ia ? 1.f : 0.f;
            const float fb = ib ? 1.f : 0.f;
            mi[k] += (int)ia + (int)ib;
            su[k]  = fmaf(fa, ua,  fmaf(fb, ub,  su[k]));
            s2[k]  = fmaf(fa, ua2, fmaf(fb, ub2, s2[k]));
            sy[k]  = fmaf(fa, ya,  fmaf(fb, yb,  sy[k]));
            q2[k]  = fmaf(fa, ya2, fmaf(fb, yb2, q2[k]));
        }
    }

    // Warp reduction via HW REDUX.SUM: quantize lane partials to 2^-20 fixed
    // point (|partial| <= 16 -> |int| <= 2^24, warp sum <= 2^29: no overflow).
    // One instruction per quantity instead of a 5-deep SHFL chain.
    int rsu[3], rs2[3], rsy[3], rq2[3];
    unsigned m[3];
#pragma unroll
    for (int k = 0; k < 3; k++) {
        rsu[k] = __reduce_add_sync(0xffffffffu, __float2int_rn(su[k] * FPSCALE));
        rs2[k] = __reduce_add_sync(0xffffffffu, __float2int_rn(s2[k] * FPSCALE));
        rsy[k] = __reduce_add_sync(0xffffffffu, __float2int_rn(sy[k] * FPSCALE));
        rq2[k] = __reduce_add_sync(0xffffffffu, __float2int_rn(q2[k] * FPSCALE));
        m[k]   = __reduce_add_sync(0xffffffffu, (unsigned)mi[k]);
    }

    if (lane == 0) {
        float    tot = 0.f;
        unsigned cnt = 0u;
#pragma unroll
        for (int k = 0; k < 3; k++) {
            const float fm  = (float)m[k];
            const float fsu = (float)rsu[k] * FPINV;
            const float fs2 = (float)rs2[k] * FPINV;
            const float fsy = (float)rsy[k] * FPINV;
            const float fq2 = (float)rq2[k] * FPINV;
            // sum_{i<j}(u_i+u_j)^2 = (m-2)*su2 + su^2
            // sum_{i<j}(y_i-y_j)^2 = m*sy2 - sy^2
            tot += (fm - 2.f) * fs2 + fsu * fsu + fm * fq2 - fsy * fsy;
            cnt += (m[k] * (m[k] - 1u)) >> 1;   // exact integer pair count
        }
        // True value is a sum of squares (>= 0); clamp rounding noise so the
        // fixed-point field can never borrow into the count field.
        tot = fmaxf(tot, 0.f);

        const unsigned long long tf  = (unsigned long long)(tot * 2048.f + 0.5f);
        const unsigned long long pkt = (tf << 32) | ((unsigned long long)cnt << 9) | 1ull;
        const unsigned long long old = atomicAdd(&g_acc, pkt);

        if ((old & 0x1FFull) == (unsigned long long)(NWARPS - 1)) {
            // Last arriver: the RMW return already holds the exact global
            // count and the full fixed-point loss sum. No fences needed.
            const unsigned long long fin  = old + pkt;
            const float fcnt = (float)((unsigned)(fin >> 9) & 0x7FFFFFu);
            const float ftot = (float)(unsigned)(fin >> 32) * (1.0f / 2048.0f);
            out[0] = __fdividef(ftot, fmaxf(fcnt, 1.0f));
            g_acc = 0ull;   // reset for next replay (published at kernel boundary)
        }
    }
}

extern "C" void kernel_launch(void* const* d_in, const int* in_sizes, int n_in,
                              void* d_out, int out_size) {
    const float4* kp  = (const float4*)d_in[0];  // [256, 512, 2] f32 -> float4 = 2 points
    const int2*   cls = (const int2*)d_in[1];    // [256, 512] i32 -> int2 = 2 classes
    float*        out = (float*)d_out;           // scalar f32

    sym_fused<<<BLOCKS, TPB>>>(kp, cls, out);
}

// round 9
// speedup vs baseline: 6.2692x; 1.0288x over previous
#include <cuda_runtime.h>

#define CENTER_X 0.5f
#define NPTS    512
#define NWARPS  256   // one warp per batch
#define BLOCKS  128
#define TPB     64    // 2 warps per block -> better SM spread (128 of 148 SMs)
#define FPSCALE 1048576.0f       // 2^20 lane-partial fixed-point scale
#define FPINV   (1.0f / 1048576.0f)

// Single packed accumulator:
//   bits [0:9)   arrival count (256 warps)
//   bits [9:32)  exact integer pair count (sum over batches)
//   bits [32:64) fixed-point loss sum, scale 2^11
// Winner decodes the final value straight from its atomicAdd return -> no
// fences, no second accumulator, order-independent (bitwise deterministic).
// Reset to 0 by the winner each launch -> identical state every graph replay.
__device__ unsigned long long g_acc = 0ull;

// ---- f32x2 packed helpers (Blackwell FFMA2: only reachable via PTX) ----
__device__ __forceinline__ unsigned long long pk2(float lo, float hi) {
    unsigned long long r;
    asm("mov.b64 %0, {%1, %2};" : "=l"(r) : "f"(lo), "f"(hi));
    return r;
}
__device__ __forceinline__ unsigned long long fma2(unsigned long long a,
                                                   unsigned long long b,
                                                   unsigned long long c) {
    unsigned long long d;
    asm("fma.rn.f32x2 %0, %1, %2, %3;" : "=l"(d) : "l"(a), "l"(b), "l"(c));
    return d;
}
__device__ __forceinline__ void upk2(unsigned long long v, float& lo, float& hi) {
    asm("mov.b64 {%0, %1}, %2;" : "=f"(lo), "=f"(hi) : "l"(v));
}

#define ONE2 0x3F8000003F800000ull   // packed (1.0f, 1.0f)

__global__ __launch_bounds__(TPB) void sym_fused(const float4* __restrict__ kp4,
                                                 const int2*   __restrict__ cls2,
                                                 float*        __restrict__ out) {
    const int lane  = threadIdx.x & 31;
    const int batch = (blockIdx.x * TPB + threadIdx.x) >> 5;  // global warp id

    const float4* kp = kp4  + batch * (NPTS / 2);
    const int2*   cl = cls2 + batch * (NPTS / 2);

    // Per symmetric class k: acc1 = packed(su, sy), acc2 = packed(su2, sy2).
    unsigned long long acc1[3] = {0ull, 0ull, 0ull};
    unsigned long long acc2[3] = {0ull, 0ull, 0ull};
    int mi[3] = {0, 0, 0};

#pragma unroll
    for (int j = 0; j < 8; j++) {
        const int    idx = j * 32 + lane;
        const float4 p   = kp[idx];
        const int2   c   = cl[idx];

        const float ua = p.x - CENTER_X, ya = p.y;
        const float ub = p.z - CENTER_X, yb = p.w;

        const unsigned long long A1 = pk2(ua, ya);
        const unsigned long long A2 = pk2(ua * ua, ya * ya);
        const unsigned long long B1 = pk2(ub, yb);
        const unsigned long long B2 = pk2(ub * ub, yb * yb);

#pragma unroll
        for (int k = 0; k < 3; k++) {
            const bool ia = (c.x == k), ib = (c.y == k);
            mi[k] += (int)ia + (int)ib;
            const unsigned long long FA = ia ? ONE2 : 0ull;
            const unsigned long long FB = ib ? ONE2 : 0ull;
            acc1[k] = fma2(FA, A1, fma2(FB, B1, acc1[k]));
            acc2[k] = fma2(FA, A2, fma2(FB, B2, acc2[k]));
        }
    }

    // Unpack, then warp-reduce via HW REDUX.SUM on 2^-20 fixed point
    // (|lane partial| <= 16 -> |int| <= 2^24, warp sum <= 2^29: no overflow).
    int rsu[3], rs2[3], rsy[3], rq2[3];
    unsigned m[3];
#pragma unroll
    for (int k = 0; k < 3; k++) {
        float su, sy, s2, q2;
        upk2(acc1[k], su, sy);
        upk2(acc2[k], s2, q2);
        rsu[k] = __reduce_add_sync(0xffffffffu, __float2int_rn(su * FPSCALE));
        rs2[k] = __reduce_add_sync(0xffffffffu, __float2int_rn(s2 * FPSCALE));
        rsy[k] = __reduce_add_sync(0xffffffffu, __float2int_rn(sy * FPSCALE));
        rq2[k] = __reduce_add_sync(0xffffffffu, __float2int_rn(q2 * FPSCALE));
        m[k]   = __reduce_add_sync(0xffffffffu, (unsigned)mi[k]);
    }

    if (lane == 0) {
        float    tot = 0.f;
        unsigned cnt = 0u;
#pragma unroll
        for (int k = 0; k < 3; k++) {
            const float fm  = (float)m[k];
            const float fsu = (float)rsu[k] * FPINV;
            const float fs2 = (float)rs2[k] * FPINV;
            const float fsy = (float)rsy[k] * FPINV;
            const float fq2 = (float)rq2[k] * FPINV;
            // sum_{i<j}(u_i+u_j)^2 = (m-2)*su2 + su^2
            // sum_{i<j}(y_i-y_j)^2 = m*sy2 - sy^2
            tot += (fm - 2.f) * fs2 + fsu * fsu + fm * fq2 - fsy * fsy;
            cnt += (m[k] * (m[k] - 1u)) >> 1;   // exact integer pair count
        }
        // True value is a sum of squares (>= 0); clamp rounding noise so the
        // fixed-point field can never borrow into the count field.
        tot = fmaxf(tot, 0.f);

        const unsigned long long tf  = (unsigned long long)(tot * 2048.f + 0.5f);
        const unsigned long long pkt = (tf << 32) | ((unsigned long long)cnt << 9) | 1ull;
        const unsigned long long old = atomicAdd(&g_acc, pkt);

        if ((old & 0x1FFull) == (unsigned long long)(NWARPS - 1)) {
            // Last arriver: the RMW return already holds the exact global
            // count and the full fixed-point loss sum. No fences needed.
            const unsigned long long fin  = old + pkt;
            const float fcnt = (float)((unsigned)(fin >> 9) & 0x7FFFFFu);
            const float ftot = (float)(unsigned)(fin >> 32) * (1.0f / 2048.0f);
            out[0] = __fdividef(ftot, fmaxf(fcnt, 1.0f));
            g_acc = 0ull;   // reset for next replay (published at kernel boundary)
        }
    }
}

extern "C" void kernel_launch(void* const* d_in, const int* in_sizes, int n_in,
                              void* d_out, int out_size) {
    const float4* kp  = (const float4*)d_in[0];  // [256, 512, 2] f32 -> float4 = 2 points
    const int2*   cls = (const int2*)d_in[1];    // [256, 512] i32 -> int2 = 2 classes
    float*        out = (float*)d_out;           // scalar f32

    sym_fused<<<BLOCKS, TPB>>>(kp, cls, out);
}

// round 10
// speedup vs baseline: 6.5200x; 1.0400x over previous
#include <cuda_runtime.h>

#define CENTER_X 0.5f
#define NPTS    512
#define NBLOCKS 256   // one block per batch
#define TPB     128   // 4 warps; each warp covers 128 points, each thread 4
#define FPSCALE 1048576.0f       // 2^20 lane-partial fixed-point scale
#define FPINV   (1.0f / 1048576.0f)

// Single packed accumulator:
//   bits [0:9)   arrival count (256 blocks)
//   bits [9:32)  exact integer pair count (sum over batches)
//   bits [32:64) fixed-point loss sum, scale 2^11
// Winner decodes the final value straight from its atomicAdd return -> no
// fences, no second accumulator, order-independent (bitwise deterministic).
// Reset to 0 by the winner each launch -> identical state every graph replay.
__device__ unsigned long long g_acc = 0ull;

__global__ __launch_bounds__(TPB) void sym_fused(const float4* __restrict__ kp4,
                                                 const int2*   __restrict__ cls2,
                                                 float*        __restrict__ out) {
    const int lane = threadIdx.x & 31;
    const int warp = threadIdx.x >> 5;
    const int base = blockIdx.x * (NPTS / 2) + warp * 64;  // pair-index base

    // Per symmetric class k in {0,1,2}: {m(int), su, su2, sy, sy2}
    float su[3] = {0.f, 0.f, 0.f};
    float s2[3] = {0.f, 0.f, 0.f};
    float sy[3] = {0.f, 0.f, 0.f};
    float q2[3] = {0.f, 0.f, 0.f};
    int   mi[3] = {0, 0, 0};

#pragma unroll
    for (int j = 0; j < 2; j++) {
        const int    idx = base + j * 32 + lane;   // coalesced per warp
        const float4 p   = kp4[idx];
        const int2   c   = cls2[idx];

        const float ua = p.x - CENTER_X, ya = p.y;
        const float ub = p.z - CENTER_X, yb = p.w;
        const float ua2 = ua * ua, ya2 = ya * ya;
        const float ub2 = ub * ub, yb2 = yb * yb;

#pragma unroll
        for (int k = 0; k < 3; k++) {
            const bool  ia = (c.x == k), ib = (c.y == k);
            const float fa = ia ? 1.f : 0.f;
            const float fb = ib ? 1.f : 0.f;
            mi[k] += (int)ia + (int)ib;
            su[k]  = fmaf(fa, ua,  fmaf(fb, ub,  su[k]));
            s2[k]  = fmaf(fa, ua2, fmaf(fb, ub2, s2[k]));
            sy[k]  = fmaf(fa, ya,  fmaf(fb, yb,  sy[k]));
            q2[k]  = fmaf(fa, ya2, fmaf(fb, yb2, q2[k]));
        }
    }

    // Warp reduction via HW REDUX.SUM on 2^-20 fixed point.
    // |lane partial| <= 4 -> |int| <= 2^22, warp sum <= 2^27: no overflow,
    // and the block combine over ints below is exact.
    __shared__ int s[4][16];   // [warp][12 stats + 3 counts], 16-int rows
    int r[15];
#pragma unroll
    for (int k = 0; k < 3; k++) {
        r[k * 4 + 0] = __reduce_add_sync(0xffffffffu, __float2int_rn(su[k] * FPSCALE));
        r[k * 4 + 1] = __reduce_add_sync(0xffffffffu, __float2int_rn(s2[k] * FPSCALE));
        r[k * 4 + 2] = __reduce_add_sync(0xffffffffu, __float2int_rn(sy[k] * FPSCALE));
        r[k * 4 + 3] = __reduce_add_sync(0xffffffffu, __float2int_rn(q2[k] * FPSCALE));
        r[12 + k]    = (int)__reduce_add_sync(0xffffffffu, (unsigned)mi[k]);
    }
    if (lane == 0) {
#pragma unroll
        for (int j = 0; j < 15; j++) s[warp][j] = r[j];
    }
    __syncthreads();

    if (threadIdx.x == 0) {
        // Exact integer combine of the 4 warp rows.
        int t[15];
#pragma unroll
        for (int j = 0; j < 15; j++)
            t[j] = s[0][j] + s[1][j] + s[2][j] + s[3][j];

        float    tot = 0.f;
        unsigned cnt = 0u;
#pragma unroll
        for (int k = 0; k < 3; k++) {
            const unsigned mk  = (unsigned)t[12 + k];
            const float    fm  = (float)mk;
            const float    fsu = (float)t[k * 4 + 0] * FPINV;
            const float    fs2 = (float)t[k * 4 + 1] * FPINV;
            const float    fsy = (float)t[k * 4 + 2] * FPINV;
            const float    fq2 = (float)t[k * 4 + 3] * FPINV;
            // sum_{i<j}(u_i+u_j)^2 = (m-2)*su2 + su^2
            // sum_{i<j}(y_i-y_j)^2 = m*sy2 - sy^2
            tot += (fm - 2.f) * fs2 + fsu * fsu + fm * fq2 - fsy * fsy;
            cnt += (mk * (mk - 1u)) >> 1;   // exact integer pair count
        }
        // True value is a sum of squares (>= 0); clamp rounding noise so the
        // fixed-point field can never borrow into the count field.
        tot = fmaxf(tot, 0.f);

        const unsigned long long tf  = (unsigned long long)(tot * 2048.f + 0.5f);
        const unsigned long long pkt = (tf << 32) | ((unsigned long long)cnt << 9) | 1ull;
        const unsigned long long old = atomicAdd(&g_acc, pkt);

        if ((old & 0x1FFull) == (unsigned long long)(NBLOCKS - 1)) {
            // Last arriver: the RMW return already holds the exact global
            // count and the full fixed-point loss sum. No fences needed.
            const unsigned long long fin  = old + pkt;
            const float fcnt = (float)((unsigned)(fin >> 9) & 0x7FFFFFu);
            const float ftot = (float)(unsigned)(fin >> 32) * (1.0f / 2048.0f);
            out[0] = __fdividef(ftot, fmaxf(fcnt, 1.0f));
            g_acc = 0ull;   // reset for next replay (published at kernel boundary)
        }
    }
}

extern "C" void kernel_launch(void* const* d_in, const int* in_sizes, int n_in,
                              void* d_out, int out_size) {
    const float4* kp  = (const float4*)d_in[0];  // [256, 512, 2] f32 -> float4 = 2 points
    const int2*   cls = (const int2*)d_in[1];    // [256, 512] i32 -> int2 = 2 classes
    float*        out = (float*)d_out;           // scalar f32

    sym_fused<<<NBLOCKS, TPB>>>(kp, cls, out);
}